// round 5
// baseline (speedup 1.0000x reference)
#include <cuda_runtime.h>
#include <math.h>

#define N_B   2
#define T_SEQ 2048
#define C_DIM 2048
#define NH    16
#define NKV   8
#define HD    128
#define BT    (N_B * T_SEQ)          /* 4096 */
#define QKVD  (C_DIM + 2 * NKV * HD) /* 4096 */
#define EPSV  1.1920929e-07f

/* ---- scratch (device globals: no allocations allowed) ---- */
__device__ float g_qkv[BT * QKVD];                 /* 64 MB */
__device__ float g_q[N_B * NH  * T_SEQ * HD];      /* 32 MB */
__device__ float g_k[N_B * NKV * T_SEQ * HD];      /* 16 MB */
__device__ float g_v[N_B * NKV * T_SEQ * HD];      /* 16 MB */
__device__ float g_y[BT * C_DIM];                  /* 32 MB */

/* ============================================================
 * SGEMM (NT): C[M,N] = A[M,K] * B[N,K]^T, fp32, 128x128x16 tiles,
 * double-buffered smem, branch-free mainloop (last slab peeled).
 * ============================================================ */

__device__ __forceinline__ void sgemm_slab_compute(
    const float (*As)[128], const float (*Bs)[128],
    int ty, int tx, float acc[8][8])
{
#pragma unroll
    for (int kk = 0; kk < 16; ++kk) {
        float a[8], b[8];
        *(float4*)(a)     = *(const float4*)&As[kk][ty * 4];
        *(float4*)(a + 4) = *(const float4*)&As[kk][64 + ty * 4];
        *(float4*)(b)     = *(const float4*)&Bs[kk][tx * 4];
        *(float4*)(b + 4) = *(const float4*)&Bs[kk][64 + tx * 4];
#pragma unroll
        for (int i = 0; i < 8; i++)
#pragma unroll
            for (int j = 0; j < 8; j++)
                acc[i][j] = fmaf(a[i], b[j], acc[i][j]);
    }
}

__global__ __launch_bounds__(256, 2)
void sgemm_nt(const float* __restrict__ A, const float* __restrict__ B,
              float* __restrict__ C, int M, int N, int K)
{
    __shared__ float As[2][16][128];
    __shared__ float Bs[2][16][128];

    const int tid = threadIdx.x;
    const int bm  = blockIdx.y * 128;
    const int bn  = blockIdx.x * 128;
    const int lr  = tid >> 1;          /* 0..127 row in tile      */
    const int lc  = (tid & 1) * 8;     /* 0 or 8 (k base offset)  */
    const int tx  = tid & 15;
    const int ty  = tid >> 4;

    const float* Ag = A + (size_t)(bm + lr) * K + lc;
    const float* Bg = B + (size_t)(bn + lr) * K + lc;

    float acc[8][8];
#pragma unroll
    for (int i = 0; i < 8; i++)
#pragma unroll
        for (int j = 0; j < 8; j++) acc[i][j] = 0.f;

    /* slab 0 -> buffer 0 */
    {
        float4 a0 = *(const float4*)(Ag);
        float4 a1 = *(const float4*)(Ag + 4);
        float4 b0 = *(const float4*)(Bg);
        float4 b1 = *(const float4*)(Bg + 4);
        As[0][lc + 0][lr] = a0.x; As[0][lc + 1][lr] = a0.y;
        As[0][lc + 2][lr] = a0.z; As[0][lc + 3][lr] = a0.w;
        As[0][lc + 4][lr] = a1.x; As[0][lc + 5][lr] = a1.y;
        As[0][lc + 6][lr] = a1.z; As[0][lc + 7][lr] = a1.w;
        Bs[0][lc + 0][lr] = b0.x; Bs[0][lc + 1][lr] = b0.y;
        Bs[0][lc + 2][lr] = b0.z; Bs[0][lc + 3][lr] = b0.w;
        Bs[0][lc + 4][lr] = b1.x; Bs[0][lc + 5][lr] = b1.y;
        Bs[0][lc + 6][lr] = b1.z; Bs[0][lc + 7][lr] = b1.w;
    }
    __syncthreads();

    int cur = 0;
    /* branch-free steady state: K/16 - 1 iterations */
    for (int k0 = 0; k0 < K - 16; k0 += 16) {
        float4 a0 = *(const float4*)(Ag + k0 + 16);
        float4 a1 = *(const float4*)(Ag + k0 + 20);
        float4 b0 = *(const float4*)(Bg + k0 + 16);
        float4 b1 = *(const float4*)(Bg + k0 + 20);

        sgemm_slab_compute(As[cur], Bs[cur], ty, tx, acc);

        int nxt = cur ^ 1;
        As[nxt][lc + 0][lr] = a0.x; As[nxt][lc + 1][lr] = a0.y;
        As[nxt][lc + 2][lr] = a0.z; As[nxt][lc + 3][lr] = a0.w;
        As[nxt][lc + 4][lr] = a1.x; As[nxt][lc + 5][lr] = a1.y;
        As[nxt][lc + 6][lr] = a1.z; As[nxt][lc + 7][lr] = a1.w;
        Bs[nxt][lc + 0][lr] = b0.x; Bs[nxt][lc + 1][lr] = b0.y;
        Bs[nxt][lc + 2][lr] = b0.z; Bs[nxt][lc + 3][lr] = b0.w;
        Bs[nxt][lc + 4][lr] = b1.x; Bs[nxt][lc + 5][lr] = b1.y;
        Bs[nxt][lc + 6][lr] = b1.z; Bs[nxt][lc + 7][lr] = b1.w;
        __syncthreads();
        cur = nxt;
    }
    /* last slab */
    sgemm_slab_compute(As[cur], Bs[cur], ty, tx, acc);

#pragma unroll
    for (int ih = 0; ih < 2; ih++)
#pragma unroll
        for (int i = 0; i < 4; i++) {
            int row = bm + ih * 64 + ty * 4 + i;
            float* Crow = C + (size_t)row * N + bn;
#pragma unroll
            for (int jh = 0; jh < 2; jh++) {
                float4 v = make_float4(acc[ih * 4 + i][jh * 4 + 0],
                                       acc[ih * 4 + i][jh * 4 + 1],
                                       acc[ih * 4 + i][jh * 4 + 2],
                                       acc[ih * 4 + i][jh * 4 + 3]);
                *(float4*)(Crow + jh * 64 + tx * 4) = v;
            }
        }
}

/* ============================================================
 * RoPE + RMSNorm + head-layout scatter.
 * One warp per 128-wide row. 32 row-jobs per (b,t):
 *   j in [0,16): q head j  -> rope+rms -> g_q[b,h,t,:]
 *   j in [16,24): k head   -> rope+rms -> g_k[b,kh,t,:]
 *   j in [24,32): v head   -> copy     -> g_v[b,kh,t,:]
 * ============================================================ */
__global__ __launch_bounds__(256)
void rope_kernel(const float* __restrict__ cosp, const float* __restrict__ sinp)
{
    int gw   = (blockIdx.x * blockDim.x + threadIdx.x) >> 5;
    int lane = threadIdx.x & 31;
    int j    = gw & 31;
    int bt   = gw >> 5;
    if (bt >= N_B * T_SEQ) return;
    int b = bt / T_SEQ;
    int t = bt % T_SEQ;

    const float* src;
    float* dst;
    if (j < 16) {
        src = g_qkv + (size_t)bt * QKVD + j * HD;
        dst = g_q + ((size_t)(b * NH + j) * T_SEQ + t) * HD;
    } else if (j < 24) {
        int kh = j - 16;
        src = g_qkv + (size_t)bt * QKVD + C_DIM + kh * HD;
        dst = g_k + ((size_t)(b * NKV + kh) * T_SEQ + t) * HD;
    } else {
        int kh = j - 24;
        src = g_qkv + (size_t)bt * QKVD + C_DIM + NKV * HD + kh * HD;
        dst = g_v + ((size_t)(b * NKV + kh) * T_SEQ + t) * HD;
        float4 v = ((const float4*)src)[lane];
        ((float4*)dst)[lane] = v;
        return;
    }

    /* rope pairs: (f, f+64), each lane handles f=lane and f=lane+32 */
    float x1a = src[lane],      x1b = src[lane + 32];
    float x2a = src[lane + 64], x2b = src[lane + 96];
    float ca = cosp[t * 64 + lane], cb = cosp[t * 64 + lane + 32];
    float sa = sinp[t * 64 + lane], sb = sinp[t * 64 + lane + 32];

    float y1a =  x1a * ca + x2a * sa;
    float y2a = -x1a * sa + x2a * ca;
    float y1b =  x1b * cb + x2b * sb;
    float y2b = -x1b * sb + x2b * cb;

    float ss = y1a * y1a + y2a * y2a + y1b * y1b + y2b * y2b;
#pragma unroll
    for (int off = 16; off > 0; off >>= 1)
        ss += __shfl_xor_sync(0xffffffffu, ss, off);

    float sc = rsqrtf(ss * (1.0f / 128.0f) + EPSV);
    dst[lane]      = y1a * sc;
    dst[lane + 32] = y1b * sc;
    dst[lane + 64] = y2a * sc;
    dst[lane + 96] = y2b * sc;
}

/* ============================================================
 * Flash attention (fp32, causal, GQA rep=2).
 * Block = (q-tile 64 rows, b*h). 256 threads.
 * smem: Qs[64][132] | U = KsT[128][68] / Vs[64][132] | Ss[64][68] | stats
 * ============================================================ */
#define QS_STR 132
#define KT_STR 68
#define VS_STR 132
#define SS_STR 68
#define ATTN_SMEM_FLOATS (64 * QS_STR + 128 * KT_STR + 64 * SS_STR + 192)
#define ATTN_SMEM_BYTES  (ATTN_SMEM_FLOATS * 4)

__global__ __launch_bounds__(256, 2)
void attn_kernel()
{
    extern __shared__ float sm[];
    float* Qs   = sm;                       /* [64][132] */
    float* U    = Qs + 64 * QS_STR;         /* KsT[128][68] then Vs[64][132] */
    float* Ss   = U + 128 * KT_STR;         /* [64][68] */
    float* rowm = Ss + 64 * SS_STR;
    float* rowl = rowm + 64;
    float* rowc = rowl + 64;

    const int tid = threadIdx.x;
    const int tx = tid & 15, ty = tid >> 4;
    const int bh = blockIdx.y;
    const int b = bh >> 4, h = bh & 15;
    const int kh = h >> 1;
    const int qt = (int)gridDim.x - 1 - (int)blockIdx.x; /* longest blocks first */
    const int q0 = qt * 64;

    const float* Qg = g_q + ((size_t)(b * NH + h) * T_SEQ + q0) * HD;
    const float* Kg = g_k + ((size_t)(b * NKV + kh) * T_SEQ) * HD;
    const float* Vg = g_v + ((size_t)(b * NKV + kh) * T_SEQ) * HD;

    for (int i = tid; i < 64 * 32; i += 256) {
        int r = i >> 5, c4 = (i & 31) << 2;
        *(float4*)(Qs + r * QS_STR + c4) = *(const float4*)(Qg + r * HD + c4);
    }
    if (tid < 64) { rowm[tid] = -1e30f; rowl[tid] = 0.f; }

    float o[4][8];
#pragma unroll
    for (int i = 0; i < 4; i++)
#pragma unroll
        for (int u = 0; u < 8; u++) o[i][u] = 0.f;

    __syncthreads();
    const float scale = 0.08838834764831845f; /* 1/sqrt(128) */

    for (int kt = 0; kt <= qt; ++kt) {
        const int k0 = kt * 64;

        /* load K transposed: KsT[d][j].
         * j = i&63 lane-major  -> scalar STS banks = const + lane  (conflict-free)
         * dc = i>>6 warp-const -> LDG row-strided; K tile is L1-resident so
         * the 7/8 re-read sectors hit L1. */
        for (int i = tid; i < 64 * 32; i += 256) {
            int j  = i & 63;
            int dc = i >> 6;               /* 0..31 d-chunk */
            float4 v = *(const float4*)(Kg + (size_t)(k0 + j) * HD + dc * 4);
            U[(dc * 4 + 0) * KT_STR + j] = v.x;
            U[(dc * 4 + 1) * KT_STR + j] = v.y;
            U[(dc * 4 + 2) * KT_STR + j] = v.z;
            U[(dc * 4 + 3) * KT_STR + j] = v.w;
        }
        __syncthreads();

        /* S = Q K^T : rows ty*4+i, cols tx*4+j */
        float s[4][4];
#pragma unroll
        for (int i = 0; i < 4; i++)
#pragma unroll
            for (int j = 0; j < 4; j++) s[i][j] = 0.f;

        for (int d0 = 0; d0 < HD; d0 += 4) {
            float qa[4][4];
#pragma unroll
            for (int i = 0; i < 4; i++)
                *(float4*)qa[i] = *(const float4*)(Qs + (ty * 4 + i) * QS_STR + d0);
#pragma unroll
            for (int dd = 0; dd < 4; dd++) {
                float4 kv4 = *(const float4*)(U + (d0 + dd) * KT_STR + tx * 4);
                float kb[4] = {kv4.x, kv4.y, kv4.z, kv4.w};
#pragma unroll
                for (int i = 0; i < 4; i++)
#pragma unroll
                    for (int j = 0; j < 4; j++)
                        s[i][j] = fmaf(qa[i][dd], kb[j], s[i][j]);
            }
        }
#pragma unroll
        for (int i = 0; i < 4; i++) {
            float4 v = make_float4(s[i][0] * scale, s[i][1] * scale,
                                   s[i][2] * scale, s[i][3] * scale);
            *(float4*)(Ss + (ty * 4 + i) * SS_STR + tx * 4) = v;
        }
        __syncthreads();

        /* load V (overwrites KsT region) while softmax runs on Ss */
        for (int i = tid; i < 64 * 32; i += 256) {
            int j = i >> 5, d4 = (i & 31) << 2;
            *(float4*)(U + j * VS_STR + d4) =
                *(const float4*)(Vg + (size_t)(k0 + j) * HD + d4);
        }

        /* online softmax: 4 threads per row; mask only on diagonal tile */
        {
            int r = tid >> 2, sub = tid & 3;
            int base = sub * 16;
            float mold = rowm[r];
            float sv[16];
            float mx = -1e30f;
            if (kt == qt) {                  /* diagonal tile: apply causal mask */
                int qglob = q0 + r;
#pragma unroll
                for (int c = 0; c < 16; c++) {
                    float v = Ss[r * SS_STR + base + c];
                    if (k0 + base + c > qglob) v = -1e30f;
                    sv[c] = v;
                    mx = fmaxf(mx, v);
                }
            } else {                         /* full tile: no mask */
#pragma unroll
                for (int c = 0; c < 16; c++) {
                    float v = Ss[r * SS_STR + base + c];
                    sv[c] = v;
                    mx = fmaxf(mx, v);
                }
            }
            mx = fmaxf(mx, __shfl_xor_sync(0xffffffffu, mx, 1));
            mx = fmaxf(mx, __shfl_xor_sync(0xffffffffu, mx, 2));
            float mnew = fmaxf(mold, mx);
            float psum = 0.f;
#pragma unroll
            for (int c = 0; c < 16; c++) {
                float p = __expf(sv[c] - mnew);
                Ss[r * SS_STR + base + c] = p;
                psum += p;
            }
            psum += __shfl_xor_sync(0xffffffffu, psum, 1);
            psum += __shfl_xor_sync(0xffffffffu, psum, 2);
            if (sub == 0) {
                float corr = __expf(mold - mnew);
                rowc[r] = corr;
                rowl[r] = rowl[r] * corr + psum;
                rowm[r] = mnew;
            }
        }
        __syncthreads();

        /* rescale O then accumulate P*V */
#pragma unroll
        for (int i = 0; i < 4; i++) {
            float c = rowc[ty * 4 + i];
#pragma unroll
            for (int u = 0; u < 8; u++) o[i][u] *= c;
        }
        for (int j0 = 0; j0 < 64; j0 += 4) {
            float pa[4][4];
#pragma unroll
            for (int i = 0; i < 4; i++)
                *(float4*)pa[i] = *(const float4*)(Ss + (ty * 4 + i) * SS_STR + j0);
#pragma unroll
            for (int jj = 0; jj < 4; jj++) {
                float4 va = *(const float4*)(U + (j0 + jj) * VS_STR + tx * 4);
                float4 vb = *(const float4*)(U + (j0 + jj) * VS_STR + 64 + tx * 4);
                float v8[8] = {va.x, va.y, va.z, va.w, vb.x, vb.y, vb.z, vb.w};
#pragma unroll
                for (int i = 0; i < 4; i++)
#pragma unroll
                    for (int u = 0; u < 8; u++)
                        o[i][u] = fmaf(pa[i][jj], v8[u], o[i][u]);
            }
        }
        __syncthreads();
    }

    /* epilogue: normalize, write y[b,t, h*128 + c] */
    float* Yb = g_y + (size_t)b * T_SEQ * C_DIM + h * HD;
#pragma unroll
    for (int i = 0; i < 4; i++) {
        int r = ty * 4 + i;
        float inv = 1.0f / rowl[r];
        float* yrow = Yb + (size_t)(q0 + r) * C_DIM;
        float4 v0 = make_float4(o[i][0] * inv, o[i][1] * inv,
                                o[i][2] * inv, o[i][3] * inv);
        float4 v1 = make_float4(o[i][4] * inv, o[i][5] * inv,
                                o[i][6] * inv, o[i][7] * inv);
        *(float4*)(yrow + tx * 4) = v0;
        *(float4*)(yrow + 64 + tx * 4) = v1;
    }
}

/* ============================================================ */
extern "C" void kernel_launch(void* const* d_in, const int* in_sizes, int n_in,
                              void* d_out, int out_size)
{
    (void)in_sizes; (void)n_in; (void)out_size;
    const float* x      = (const float*)d_in[0];
    const float* w_attn = (const float*)d_in[1];
    const float* w_proj = (const float*)d_in[2];
    const float* cosp   = (const float*)d_in[3];
    const float* sinp   = (const float*)d_in[4];
    float* out = (float*)d_out;

    float *qkv_p, *y_p;
    cudaGetSymbolAddress((void**)&qkv_p, g_qkv);
    cudaGetSymbolAddress((void**)&y_p, g_y);

    cudaFuncSetAttribute(attn_kernel,
                         cudaFuncAttributeMaxDynamicSharedMemorySize,
                         ATTN_SMEM_BYTES);

    dim3 g1(QKVD / 128, BT / 128);      /* 32 x 32 */
    sgemm_nt<<<g1, 256>>>(x, w_attn, qkv_p, BT, QKVD, C_DIM);

    int nwarps = N_B * T_SEQ * 32;
    rope_kernel<<<nwarps / 8, 256>>>(cosp, sinp);

    dim3 ga(T_SEQ / 64, N_B * NH);      /* 32 x 32 */
    attn_kernel<<<ga, 256, ATTN_SMEM_BYTES>>>();

    dim3 g2(C_DIM / 128, BT / 128);     /* 16 x 32 */
    sgemm_nt<<<g2, 256>>>(y_p, w_proj, out, BT, C_DIM, C_DIM);
}

// round 13
// speedup vs baseline: 1.0007x; 1.0007x over previous
#include <cuda_runtime.h>
#include <math.h>
#include <stdint.h>

#define N_B   2
#define T_SEQ 2048
#define C_DIM 2048
#define NH    16
#define NKV   8
#define HD    128
#define BT    (N_B * T_SEQ)          /* 4096 */
#define QKVD  (C_DIM + 2 * NKV * HD) /* 4096 */
#define EPSV  1.1920929e-07f

/* ---- scratch (device globals: no allocations allowed) ---- */
__device__ float g_qkv[BT * QKVD];
__device__ float g_q[N_B * NH  * T_SEQ * HD];
__device__ float g_k[N_B * NKV * T_SEQ * HD];
__device__ float g_v[N_B * NKV * T_SEQ * HD];
__device__ float g_y[BT * C_DIM];

/* ============================================================
 * 3xTF32 helpers: x = hi + lo, products hi*hi + hi*lo + lo*hi
 * ============================================================ */
__device__ __forceinline__ uint32_t f2tf32(float x) {
    uint32_t r;
    asm("cvt.rna.tf32.f32 %0, %1;" : "=r"(r) : "f"(x));
    return r;
}

__device__ __forceinline__ void split_tf32(float x, uint32_t& hi, uint32_t& lo) {
    hi = f2tf32(x);
    float r = x - __uint_as_float(hi);
    lo = f2tf32(r);
}

__device__ __forceinline__ void mma_tf32(float d[4], const uint32_t a[4],
                                         const uint32_t b[2]) {
    asm volatile(
        "mma.sync.aligned.m16n8k8.row.col.f32.tf32.tf32.f32 "
        "{%0,%1,%2,%3}, {%4,%5,%6,%7}, {%8,%9}, {%0,%1,%2,%3};"
        : "+f"(d[0]), "+f"(d[1]), "+f"(d[2]), "+f"(d[3])
        : "r"(a[0]), "r"(a[1]), "r"(a[2]), "r"(a[3]),
          "r"(b[0]), "r"(b[1]));
}

__device__ __forceinline__ void mma3_tf32(float d[4],
                                          const uint32_t ah[4], const uint32_t al[4],
                                          const uint32_t bh[2], const uint32_t bl[2]) {
    mma_tf32(d, ah, bh);
    mma_tf32(d, ah, bl);
    mma_tf32(d, al, bh);
}

/* ============================================================
 * 3xTF32 tensor-core GEMM (NT): C[M,N] = A[M,K] * B[N,K]^T
 * CTA 128x128, 8 warps of 64x32. smem holds raw fp32 (split on load).
 * ============================================================ */
#define BK   16
#define KSTR 20
#define GEMM_SMEM_BYTES (4 * 128 * KSTR * 4)   /* 40960 B */

__device__ __forceinline__ void gemm_store_slab(float* dstA, float* dstB,
                                                int lrow, int lcol8,
                                                const float4 a[2], const float4 b[2])
{
    float* Ad = dstA + lrow * KSTR + lcol8;
    float* Bd = dstB + lrow * KSTR + lcol8;
    Ad[0] = a[0].x; Ad[1] = a[0].y; Ad[2] = a[0].z; Ad[3] = a[0].w;
    Ad[4] = a[1].x; Ad[5] = a[1].y; Ad[6] = a[1].z; Ad[7] = a[1].w;
    Bd[0] = b[0].x; Bd[1] = b[0].y; Bd[2] = b[0].z; Bd[3] = b[0].w;
    Bd[4] = b[1].x; Bd[5] = b[1].y; Bd[6] = b[1].z; Bd[7] = b[1].w;
}

__device__ __forceinline__ void gemm_slab_mma(const float* Abuf, const float* Bbuf,
                                              int wr, int wc, int lane,
                                              float acc[4][4][4])
{
    const int r4 = lane >> 2, c4 = lane & 3;
#pragma unroll
    for (int ks = 0; ks < 2; ++ks) {
        const int k0 = ks * 8;
        uint32_t ah[4][4], al[4][4];
#pragma unroll
        for (int mi = 0; mi < 4; ++mi) {
            int rb = wr * 64 + mi * 16 + r4;
            split_tf32(Abuf[rb * KSTR + k0 + c4],           ah[mi][0], al[mi][0]);
            split_tf32(Abuf[(rb + 8) * KSTR + k0 + c4],     ah[mi][1], al[mi][1]);
            split_tf32(Abuf[rb * KSTR + k0 + c4 + 4],       ah[mi][2], al[mi][2]);
            split_tf32(Abuf[(rb + 8) * KSTR + k0 + c4 + 4], ah[mi][3], al[mi][3]);
        }
#pragma unroll
        for (int ni = 0; ni < 4; ++ni) {
            int nb = wc * 32 + ni * 8 + r4;
            uint32_t bh[2], bl[2];
            split_tf32(Bbuf[nb * KSTR + k0 + c4],     bh[0], bl[0]);
            split_tf32(Bbuf[nb * KSTR + k0 + c4 + 4], bh[1], bl[1]);
#pragma unroll
            for (int mi = 0; mi < 4; ++mi)
                mma3_tf32(acc[mi][ni], ah[mi], al[mi], bh, bl);
        }
    }
}

__global__ __launch_bounds__(256, 2)
void gemm_tf32(const float* __restrict__ A, const float* __restrict__ B,
               float* __restrict__ C, int M, int N, int K)
{
    extern __shared__ float sm[];
    float* Ab[2] = {sm,             sm + 128 * KSTR};
    float* Bb[2] = {sm + 2 * 128 * KSTR, sm + 3 * 128 * KSTR};

    const int tid  = threadIdx.x;
    const int lane = tid & 31;
    const int warp = tid >> 5;
    const int wr   = warp >> 2;
    const int wc   = warp & 3;
    const int bm   = blockIdx.y * 128;
    const int bn   = blockIdx.x * 128;

    const int lrow  = tid >> 1;
    const int lcol8 = (tid & 1) * 8;

    const float* Ag = A + (size_t)(bm + lrow) * K + lcol8;
    const float* Bg = B + (size_t)(bn + lrow) * K + lcol8;

    float acc[4][4][4];
#pragma unroll
    for (int mi = 0; mi < 4; ++mi)
#pragma unroll
        for (int ni = 0; ni < 4; ++ni)
#pragma unroll
            for (int u = 0; u < 4; ++u) acc[mi][ni][u] = 0.f;

    {
        float4 a[2], b[2];
        a[0] = *(const float4*)(Ag);     a[1] = *(const float4*)(Ag + 4);
        b[0] = *(const float4*)(Bg);     b[1] = *(const float4*)(Bg + 4);
        gemm_store_slab(Ab[0], Bb[0], lrow, lcol8, a, b);
    }
    __syncthreads();

    int cur = 0;
    for (int k0 = 0; k0 < K - BK; k0 += BK) {
        float4 a[2], b[2];
        a[0] = *(const float4*)(Ag + k0 + BK);
        a[1] = *(const float4*)(Ag + k0 + BK + 4);
        b[0] = *(const float4*)(Bg + k0 + BK);
        b[1] = *(const float4*)(Bg + k0 + BK + 4);

        gemm_slab_mma(Ab[cur], Bb[cur], wr, wc, lane, acc);

        int nxt = cur ^ 1;
        gemm_store_slab(Ab[nxt], Bb[nxt], lrow, lcol8, a, b);
        __syncthreads();
        cur = nxt;
    }
    gemm_slab_mma(Ab[cur], Bb[cur], wr, wc, lane, acc);

#pragma unroll
    for (int mi = 0; mi < 4; ++mi) {
        int row = bm + wr * 64 + mi * 16 + (lane >> 2);
#pragma unroll
        for (int ni = 0; ni < 4; ++ni) {
            int col = bn + wc * 32 + ni * 8 + 2 * (lane & 3);
            *(float2*)(C + (size_t)row * N + col) =
                make_float2(acc[mi][ni][0], acc[mi][ni][1]);
            *(float2*)(C + (size_t)(row + 8) * N + col) =
                make_float2(acc[mi][ni][2], acc[mi][ni][3]);
        }
    }
}

/* ============================================================
 * RoPE + RMSNorm + head-layout scatter (unchanged)
 * ============================================================ */
__global__ __launch_bounds__(256)
void rope_kernel(const float* __restrict__ cosp, const float* __restrict__ sinp)
{
    int gw   = (blockIdx.x * blockDim.x + threadIdx.x) >> 5;
    int lane = threadIdx.x & 31;
    int j    = gw & 31;
    int bt   = gw >> 5;
    if (bt >= N_B * T_SEQ) return;
    int b = bt / T_SEQ;
    int t = bt % T_SEQ;

    const float* src;
    float* dst;
    if (j < 16) {
        src = g_qkv + (size_t)bt * QKVD + j * HD;
        dst = g_q + ((size_t)(b * NH + j) * T_SEQ + t) * HD;
    } else if (j < 24) {
        int kh = j - 16;
        src = g_qkv + (size_t)bt * QKVD + C_DIM + kh * HD;
        dst = g_k + ((size_t)(b * NKV + kh) * T_SEQ + t) * HD;
    } else {
        int kh = j - 24;
        src = g_qkv + (size_t)bt * QKVD + C_DIM + NKV * HD + kh * HD;
        dst = g_v + ((size_t)(b * NKV + kh) * T_SEQ + t) * HD;
        float4 v = ((const float4*)src)[lane];
        ((float4*)dst)[lane] = v;
        return;
    }

    float x1a = src[lane],      x1b = src[lane + 32];
    float x2a = src[lane + 64], x2b = src[lane + 96];
    float ca = cosp[t * 64 + lane], cb = cosp[t * 64 + lane + 32];
    float sa = sinp[t * 64 + lane], sb = sinp[t * 64 + lane + 32];

    float y1a =  x1a * ca + x2a * sa;
    float y2a = -x1a * sa + x2a * ca;
    float y1b =  x1b * cb + x2b * sb;
    float y2b = -x1b * sb + x2b * cb;

    float ss = y1a * y1a + y2a * y2a + y1b * y1b + y2b * y2b;
#pragma unroll
    for (int off = 16; off > 0; off >>= 1)
        ss += __shfl_xor_sync(0xffffffffu, ss, off);

    float sc = rsqrtf(ss * (1.0f / 128.0f) + EPSV);
    dst[lane]      = y1a * sc;
    dst[lane + 32] = y1b * sc;
    dst[lane + 64] = y2a * sc;
    dst[lane + 96] = y2b * sc;
}

/* ============================================================
 * Flash attention, 3xTF32 MMA for S=QK^T and O=P*V.
 * Scalar online softmax unchanged.
 * ============================================================ */
#define QS_STR 132
#define KS_STR 132
#define VS_STR 136
#define SS_STR 68
#define U_FLOATS (64 * VS_STR)   /* 8704 >= 64*132 */
#define ATTN_SMEM_FLOATS (64 * QS_STR + U_FLOATS + 64 * SS_STR + 192)
#define ATTN_SMEM_BYTES  (ATTN_SMEM_FLOATS * 4)

__global__ __launch_bounds__(256, 2)
void attn_kernel()
{
    extern __shared__ float sm[];
    float* Qs   = sm;                       /* [64][132] */
    float* U    = Qs + 64 * QS_STR;         /* K [64][132] then V [64][136] */
    float* Ss   = U + U_FLOATS;             /* [64][68] */
    float* rowm = Ss + 64 * SS_STR;
    float* rowl = rowm + 64;
    float* rowc = rowl + 64;

    const int tid  = threadIdx.x;
    const int lane = tid & 31;
    const int warp = tid >> 5;
    const int wm   = warp >> 1;
    const int wn   = warp & 1;
    const int r4   = lane >> 2;
    const int c4   = lane & 3;
    const int R    = wm * 16 + r4;

    const int bh = blockIdx.y;
    const int b = bh >> 4, h = bh & 15;
    const int kh = h >> 1;
    const int qt = (int)gridDim.x - 1 - (int)blockIdx.x;
    const int q0 = qt * 64;

    const float* Qg = g_q + ((size_t)(b * NH + h) * T_SEQ + q0) * HD;
    const float* Kg = g_k + ((size_t)(b * NKV + kh) * T_SEQ) * HD;
    const float* Vg = g_v + ((size_t)(b * NKV + kh) * T_SEQ) * HD;

    for (int i = tid; i < 64 * 32; i += 256) {
        int r = i >> 5, d4 = (i & 31) << 2;
        *(float4*)(Qs + r * QS_STR + d4) = *(const float4*)(Qg + r * HD + d4);
    }
    if (tid < 64) { rowm[tid] = -1e30f; rowl[tid] = 0.f; }

    float o[8][4];
#pragma unroll
    for (int ni = 0; ni < 8; ni++)
#pragma unroll
        for (int u = 0; u < 4; u++) o[ni][u] = 0.f;

    __syncthreads();
    const float scale = 0.08838834764831845f; /* 1/sqrt(128) */

    for (int kt = 0; kt <= qt; ++kt) {
        const int k0 = kt * 64;

        /* load K rows [64][128] into U stride 132 */
        for (int i = tid; i < 64 * 32; i += 256) {
            int j = i >> 5, d4 = (i & 31) << 2;
            *(float4*)(U + j * KS_STR + d4) =
                *(const float4*)(Kg + (size_t)(k0 + j) * HD + d4);
        }
        __syncthreads();

        /* S = Q K^T via 3xTF32 MMA: m16 x 4 n8 tiles, k=128 */
        {
            float s[4][4];
#pragma unroll
            for (int ni = 0; ni < 4; ni++)
#pragma unroll
                for (int u = 0; u < 4; u++) s[ni][u] = 0.f;

#pragma unroll
            for (int ks = 0; ks < 16; ++ks) {
                const int kk = ks * 8;
                uint32_t ah[4], al[4];
                split_tf32(Qs[R * QS_STR + kk + c4],           ah[0], al[0]);
                split_tf32(Qs[(R + 8) * QS_STR + kk + c4],     ah[1], al[1]);
                split_tf32(Qs[R * QS_STR + kk + c4 + 4],       ah[2], al[2]);
                split_tf32(Qs[(R + 8) * QS_STR + kk + c4 + 4], ah[3], al[3]);
#pragma unroll
                for (int ni = 0; ni < 4; ++ni) {
                    int nb = wn * 32 + ni * 8 + r4;
                    uint32_t bhh[2], bll[2];
                    split_tf32(U[nb * KS_STR + kk + c4],     bhh[0], bll[0]);
                    split_tf32(U[nb * KS_STR + kk + c4 + 4], bhh[1], bll[1]);
                    mma3_tf32(s[ni], ah, al, bhh, bll);
                }
            }
#pragma unroll
            for (int ni = 0; ni < 4; ++ni) {
                int cb = wn * 32 + ni * 8 + 2 * c4;
                *(float2*)(Ss + R * SS_STR + cb) =
                    make_float2(s[ni][0] * scale, s[ni][1] * scale);
                *(float2*)(Ss + (R + 8) * SS_STR + cb) =
                    make_float2(s[ni][2] * scale, s[ni][3] * scale);
            }
        }
        __syncthreads();

        /* load V rows [64][128] into U stride 136 (K dead) */
        for (int i = tid; i < 64 * 32; i += 256) {
            int j = i >> 5, d4 = (i & 31) << 2;
            *(float4*)(U + j * VS_STR + d4) =
                *(const float4*)(Vg + (size_t)(k0 + j) * HD + d4);
        }

        /* online softmax (unchanged) */
        {
            int r = tid >> 2, sub = tid & 3;
            int base = sub * 16;
            float mold = rowm[r];
            float sv[16];
            float mx = -1e30f;
            if (kt == qt) {
                int qglob = q0 + r;
#pragma unroll
                for (int c = 0; c < 16; c++) {
                    float v = Ss[r * SS_STR + base + c];
                    if (k0 + base + c > qglob) v = -1e30f;
                    sv[c] = v;
                    mx = fmaxf(mx, v);
                }
            } else {
#pragma unroll
                for (int c = 0; c < 16; c++) {
                    float v = Ss[r * SS_STR + base + c];
                    sv[c] = v;
                    mx = fmaxf(mx, v);
                }
            }
            mx = fmaxf(mx, __shfl_xor_sync(0xffffffffu, mx, 1));
            mx = fmaxf(mx, __shfl_xor_sync(0xffffffffu, mx, 2));
            float mnew = fmaxf(mold, mx);
            float psum = 0.f;
#pragma unroll
            for (int c = 0; c < 16; c++) {
                float p = __expf(sv[c] - mnew);
                Ss[r * SS_STR + base + c] = p;
                psum += p;
            }
            psum += __shfl_xor_sync(0xffffffffu, psum, 1);
            psum += __shfl_xor_sync(0xffffffffu, psum, 2);
            if (sub == 0) {
                float corr = __expf(mold - mnew);
                rowc[r] = corr;
                rowl[r] = rowl[r] * corr + psum;
                rowm[r] = mnew;
            }
        }
        __syncthreads();

        /* rescale O, then O += P V via 3xTF32 MMA: m16 x 8 n8 tiles, k=64 */
        {
            float c0 = rowc[R], c1 = rowc[R + 8];
#pragma unroll
            for (int ni = 0; ni < 8; ni++) {
                o[ni][0] *= c0; o[ni][1] *= c0;
                o[ni][2] *= c1; o[ni][3] *= c1;
            }
#pragma unroll
            for (int ks = 0; ks < 8; ++ks) {
                const int kk = ks * 8;
                uint32_t ah[4], al[4];
                split_tf32(Ss[R * SS_STR + kk + c4],           ah[0], al[0]);
                split_tf32(Ss[(R + 8) * SS_STR + kk + c4],     ah[1], al[1]);
                split_tf32(Ss[R * SS_STR + kk + c4 + 4],       ah[2], al[2]);
                split_tf32(Ss[(R + 8) * SS_STR + kk + c4 + 4], ah[3], al[3]);
#pragma unroll
                for (int ni = 0; ni < 8; ++ni) {
                    int colb = wn * 64 + ni * 8 + r4;
                    uint32_t bhh[2], bll[2];
                    split_tf32(U[(kk + c4) * VS_STR + colb],     bhh[0], bll[0]);
                    split_tf32(U[(kk + c4 + 4) * VS_STR + colb], bhh[1], bll[1]);
                    mma3_tf32(o[ni], ah, al, bhh, bll);
                }
            }
        }
        __syncthreads();
    }

    /* epilogue: normalize, write y */
    {
        float inv0 = 1.0f / rowl[R];
        float inv1 = 1.0f / rowl[R + 8];
        float* y0 = g_y + (size_t)b * T_SEQ * C_DIM
                  + (size_t)(q0 + R) * C_DIM + h * HD;
        float* y1 = g_y + (size_t)b * T_SEQ * C_DIM
                  + (size_t)(q0 + R + 8) * C_DIM + h * HD;
#pragma unroll
        for (int ni = 0; ni < 8; ++ni) {
            int col = wn * 64 + ni * 8 + 2 * c4;
            *(float2*)(y0 + col) = make_float2(o[ni][0] * inv0, o[ni][1] * inv0);
            *(float2*)(y1 + col) = make_float2(o[ni][2] * inv1, o[ni][3] * inv1);
        }
    }
}

/* ============================================================ */
extern "C" void kernel_launch(void* const* d_in, const int* in_sizes, int n_in,
                              void* d_out, int out_size)
{
    (void)in_sizes; (void)n_in; (void)out_size;
    const float* x      = (const float*)d_in[0];
    const float* w_attn = (const float*)d_in[1];
    const float* w_proj = (const float*)d_in[2];
    const float* cosp   = (const float*)d_in[3];
    const float* sinp   = (const float*)d_in[4];
    float* out = (float*)d_out;

    float *qkv_p, *y_p;
    cudaGetSymbolAddress((void**)&qkv_p, g_qkv);
    cudaGetSymbolAddress((void**)&y_p, g_y);

    cudaFuncSetAttribute(attn_kernel,
                         cudaFuncAttributeMaxDynamicSharedMemorySize,
                         ATTN_SMEM_BYTES);

    dim3 g1(QKVD / 128, BT / 128);      /* 32 x 32 */
    gemm_tf32<<<g1, 256, GEMM_SMEM_BYTES>>>(x, w_attn, qkv_p, BT, QKVD, C_DIM);

    int nwarps = N_B * T_SEQ * 32;
    rope_kernel<<<nwarps / 8, 256>>>(cosp, sinp);

    dim3 ga(T_SEQ / 64, N_B * NH);      /* 32 x 32 */
    attn_kernel<<<ga, 256, ATTN_SMEM_BYTES>>>();

    dim3 g2(C_DIM / 128, BT / 128);     /* 16 x 32 */
    gemm_tf32<<<g2, 256, GEMM_SMEM_BYTES>>>(y_p, w_proj, out, BT, C_DIM, C_DIM);
}